// round 16
// baseline (speedup 1.0000x reference)
#include <cuda_runtime.h>
#include <cuda_bf16.h>

#define BB 8
#define TT 512
#define CC 128
#define HH 1024
#define GBLK 148
#define GW 7

typedef unsigned long long ull;
typedef unsigned short ushort_t;

// ---------------- f32x2 helpers (decoder kernels) ----------------
__device__ __forceinline__ ull dup2(float x)
{
    ull r;
    asm("mov.b64 %0, {%1, %1};" : "=l"(r) : "f"(x));
    return r;
}
__device__ __forceinline__ ull ffma2(ull a, ull b, ull c)
{
    ull d;
    asm("fma.rn.f32x2 %0, %1, %2, %3;" : "=l"(d) : "l"(a), "l"(b), "l"(c));
    return d;
}
__device__ __forceinline__ float2 unpk2(ull v)
{
    float2 f;
    asm("mov.b64 {%0, %1}, %2;" : "=f"(f.x), "=f"(f.y) : "l"(v));
    return f;
}

// ---------------- static scratch ----------------
__device__ float g_xg[BB * TT * 3 * HH];
__device__ ushort_t g_hhi[2][BB * HH];
__device__ ushort_t g_hlo[2][BB * HH];
__device__ float g_emb2[BB * CC * TT * 8];
__device__ float g_x3[BB * CC * TT * 8];
__device__ float g_e3x[BB * CC * TT * 16];
__device__ float g_x2[BB * CC * TT * 16];
__device__ float g_e2x[BB * CC * TT * 32];
__device__ float g_x1[BB * CC * TT * 32];
__device__ float g_e1x[BB * CC * TT * 64];
__device__ float g_p0[BB * CC * TT * 64];
__device__ float g_wtT3[3 * CC * CC];
__device__ float g_wtT2[3 * CC * CC];
__device__ float g_wtT1[3 * CC * CC];
__device__ unsigned short g_Ah[BB * TT * HH];
__device__ unsigned short g_Al[BB * TT * HH];
__device__ unsigned short g_Wh[3 * HH * HH];
__device__ unsigned short g_Wl[3 * HH * HH];
__device__ unsigned g_arrive[GBLK * 32];    // per-block arrival slots, 128B stride
__device__ unsigned g_bar_gen;

// ---------------- barrier state reset (per launch) ----------------
__global__ void k_reset()
{
    int i = blockIdx.x * 256 + threadIdx.x;
    if (i < GBLK * 32) g_arrive[i] = 0;
    if (i == 0) g_bar_gen = 0;
}

// ---------------- distributed-arrival grid barrier ----------------
// Arrival: per-block release-store to a distinct L2 line (no atomic
// serialization). Block 0 aggregates (threads 1..147 poll slots), then
// publishes g_bar_gen; other blocks poll g_bar_gen.
__device__ __forceinline__ void grid_barrier(unsigned my_gen)
{
    __syncthreads();
    if (blockIdx.x == 0) {
        int tid = threadIdx.x;
        if (tid > 0 && tid < GBLK) {
            unsigned cur;
            do {
                asm volatile("ld.acquire.gpu.u32 %0, [%1];"
                             : "=r"(cur) : "l"(&g_arrive[tid * 32]) : "memory");
            } while ((int)(cur - my_gen) < 0);
        }
        __syncthreads();
        if (tid == 0)
            asm volatile("st.release.gpu.u32 [%0], %1;"
                         :: "l"(&g_bar_gen), "r"(my_gen) : "memory");
    } else {
        if (threadIdx.x == 0) {
            asm volatile("st.release.gpu.u32 [%0], %1;"
                         :: "l"(&g_arrive[blockIdx.x * 32]), "r"(my_gen) : "memory");
            unsigned cur;
            do {
                asm volatile("ld.acquire.gpu.u32 %0, [%1];"
                             : "=r"(cur) : "l"(&g_bar_gen) : "memory");
            } while ((int)(cur - my_gen) < 0);
        }
        __syncthreads();
    }
}

// ---------------- splitting helper ----------------
__device__ __forceinline__ void split1(float v, unsigned short& h, unsigned short& l)
{
    __nv_bfloat16 bh = __float2bfloat16(v);
    float r = v - __bfloat162float(bh);
    __nv_bfloat16 bl = __float2bfloat16(r);
    h = *(unsigned short*)&bh;
    l = *(unsigned short*)&bl;
}

// ---------------- bf16 hi/lo split: fp32 tensor -> (hi, lo) ----------------
__global__ __launch_bounds__(256) void k_split(const float4* __restrict__ src,
                                               ushort4* __restrict__ hi,
                                               ushort4* __restrict__ lo,
                                               int n4)
{
    int i = blockIdx.x * 256 + threadIdx.x;
    if (i >= n4) return;
    float4 v = src[i];
    float f[4] = { v.x, v.y, v.z, v.w };
    unsigned short h[4], l[4];
#pragma unroll
    for (int q = 0; q < 4; ++q) split1(f[q], h[q], l[q]);
    hi[i] = make_ushort4(h[0], h[1], h[2], h[3]);
    lo[i] = make_ushort4(l[0], l[1], l[2], l[3]);
}

// ---------------- mma helpers (sm_80-baseline PTX) ----------------
__device__ __forceinline__ unsigned smem_u32(const void* p)
{
    unsigned a;
    asm("{ .reg .u64 t; cvta.to.shared.u64 t, %1; cvt.u32.u64 %0, t; }"
        : "=r"(a) : "l"(p));
    return a;
}
__device__ __forceinline__ void ldsm4(unsigned* r, unsigned addr)
{
    asm volatile("ldmatrix.sync.aligned.m8n8.x4.shared.b16 {%0,%1,%2,%3}, [%4];"
        : "=r"(r[0]), "=r"(r[1]), "=r"(r[2]), "=r"(r[3]) : "r"(addr));
}
__device__ __forceinline__ void ldsm2(unsigned* r, unsigned addr)
{
    asm volatile("ldmatrix.sync.aligned.m8n8.x2.shared.b16 {%0,%1}, [%2];"
        : "=r"(r[0]), "=r"(r[1]) : "r"(addr));
}
__device__ __forceinline__ void mma16816(float* d, const unsigned* a, const unsigned* b)
{
    asm volatile("mma.sync.aligned.m16n8k16.row.col.f32.bf16.bf16.f32 "
        "{%0,%1,%2,%3}, {%4,%5,%6,%7}, {%8,%9}, {%0,%1,%2,%3};"
        : "+f"(d[0]), "+f"(d[1]), "+f"(d[2]), "+f"(d[3])
        : "r"(a[0]), "r"(a[1]), "r"(a[2]), "r"(a[3]), "r"(b[0]), "r"(b[1]));
}

// ---------------- xg = emb @ Wih^T + bih : mma.sync split-bf16 ----------------
__global__ __launch_bounds__(256) void k_xg_mma(const float* __restrict__ bias)
{
    __shared__ __align__(16) unsigned short sAh[128][40];
    __shared__ __align__(16) unsigned short sAl[128][40];
    __shared__ __align__(16) unsigned short sWh[64][40];
    __shared__ __align__(16) unsigned short sWl[64][40];
    int tid = threadIdx.x, lane = tid & 31, wid = tid >> 5;
    int wm = wid >> 1, wn = wid & 1;
    int m0 = blockIdx.y * 128, n0 = blockIdx.x * 64;

    float acc[2][4][4];
#pragma unroll
    for (int mi = 0; mi < 2; ++mi)
#pragma unroll
        for (int ni = 0; ni < 4; ++ni)
#pragma unroll
            for (int q = 0; q < 4; ++q) acc[mi][ni][q] = 0.f;

    for (int kc = 0; kc < HH; kc += 32) {
        __syncthreads();
#pragma unroll
        for (int i = 0; i < 6; ++i) {
            int idx = tid + i * 256;
            const uint4* src;
            unsigned short* dst;
            if (idx < 512) {
                int row = idx >> 2, c8 = (idx & 3) * 8;
                src = (const uint4*)&g_Ah[(size_t)(m0 + row) * HH + kc + c8];
                dst = &sAh[row][c8];
            } else if (idx < 1024) {
                int e = idx - 512;
                int row = e >> 2, c8 = (e & 3) * 8;
                src = (const uint4*)&g_Al[(size_t)(m0 + row) * HH + kc + c8];
                dst = &sAl[row][c8];
            } else if (idx < 1280) {
                int e = idx - 1024;
                int row = e >> 2, c8 = (e & 3) * 8;
                src = (const uint4*)&g_Wh[(size_t)(n0 + row) * HH + kc + c8];
                dst = &sWh[row][c8];
            } else {
                int e = idx - 1280;
                int row = e >> 2, c8 = (e & 3) * 8;
                src = (const uint4*)&g_Wl[(size_t)(n0 + row) * HH + kc + c8];
                dst = &sWl[row][c8];
            }
            *(uint4*)dst = *src;
        }
        __syncthreads();

#pragma unroll
        for (int ks = 0; ks < 2; ++ks) {
            int k0 = ks * 16;
            unsigned ah[2][4], al[2][4];
#pragma unroll
            for (int mi = 0; mi < 2; ++mi) {
                int m = wm * 32 + mi * 16 + (lane & 15);
                int kk = k0 + (lane >> 4) * 8;
                ldsm4(ah[mi], smem_u32(&sAh[m][kk]));
                ldsm4(al[mi], smem_u32(&sAl[m][kk]));
            }
            unsigned bh[4][2], bl[4][2];
#pragma unroll
            for (int ni = 0; ni < 4; ++ni) {
                int r = lane & 15;
                int n = wn * 32 + ni * 8 + (r & 7);
                int kk = k0 + (r >> 3) * 8;
                ldsm2(bh[ni], smem_u32(&sWh[n][kk]));
                ldsm2(bl[ni], smem_u32(&sWl[n][kk]));
            }
#pragma unroll
            for (int mi = 0; mi < 2; ++mi)
#pragma unroll
                for (int ni = 0; ni < 4; ++ni) {
                    mma16816(acc[mi][ni], ah[mi], bh[ni]);
                    mma16816(acc[mi][ni], ah[mi], bl[ni]);
                    mma16816(acc[mi][ni], al[mi], bh[ni]);
                }
        }
    }
    int gr = lane >> 2, gc = (lane & 3) * 2;
#pragma unroll
    for (int mi = 0; mi < 2; ++mi)
#pragma unroll
        for (int ni = 0; ni < 4; ++ni) {
            int m = m0 + wm * 32 + mi * 16 + gr;
            int n = n0 + wn * 32 + ni * 8 + gc;
            float b0 = bias[n], b1 = bias[n + 1];
            float2 v0 = { acc[mi][ni][0] + b0, acc[mi][ni][1] + b1 };
            float2 v1 = { acc[mi][ni][2] + b0, acc[mi][ni][3] + b1 };
            *(float2*)&g_xg[(size_t)m * (3 * HH) + n] = v0;
            *(float2*)&g_xg[(size_t)(m + 8) * (3 * HH) + n] = v1;
        }
}

// ---------------- persistent GRU: reg-resident weight fragments ----------------
#define GRU_STRIDE 1032
#define OFF_HH 0
#define OFF_HL 16512
#define OFF_RED 33024
#define OFF_G 41216
#define GRU_SMEM 42240
#define ST_STRIDE 136

__global__ __launch_bounds__(256) void k_gru(const float* __restrict__ h0,
                                             const float* __restrict__ Whh,
                                             const float* __restrict__ bhh,
                                             float* __restrict__ outHT)
{
    extern __shared__ char gsm[];
    ushort_t (*sHh)[GRU_STRIDE] = (ushort_t(*)[GRU_STRIDE])(gsm + OFF_HH);
    ushort_t (*sHl)[GRU_STRIDE] = (ushort_t(*)[GRU_STRIDE])(gsm + OFF_HL);
    float (*sRed)[32][8] = (float(*)[32][8])(gsm + OFF_RED);
    float (*sG)[8] = (float(*)[8])(gsm + OFF_G);
    ushort_t (*stH)[ST_STRIDE] = (ushort_t(*)[ST_STRIDE])(gsm + 0);
    ushort_t (*stL)[ST_STRIDE] = (ushort_t(*)[ST_STRIDE])(gsm + 32 * ST_STRIDE * 2);

    int tid = threadIdx.x, lane = tid & 31, wid = tid >> 5;

    int eu = tid >> 3, eb = tid & 7;
    int ej = blockIdx.x * GW + eu;
    bool epv = (tid < 56) && (ej < HH);
    float br_ = 0.f, bz_ = 0.f, bn_ = 0.f, hprev = 0.f;
    int ec = ej & 127, ef = ej >> 7;
    if (epv) {
        br_ = bhh[ej]; bz_ = bhh[ej + HH]; bn_ = bhh[ej + 2 * HH];
        hprev = h0[eb * HH + ej];
    }

    // prologue: weight fragments -> registers via staged chunks
    unsigned ah[8][2][4], al[8][2][4];
    for (int c = 0; c < 8; ++c) {
        __syncthreads();
        for (int idx = tid; idx < 4096; idx += 256) {
            int row = idx >> 7, x = idx & 127;
            float v = 0.f;
            if (row < 21) {
                int unit = row / 3, gate = row - unit * 3;
                int j = blockIdx.x * GW + unit;
                if (j < HH) v = Whh[(size_t)(j + gate * HH) * HH + c * 128 + x];
            }
            unsigned short h, l;
            split1(v, h, l);
            stH[row][x] = h;
            stL[row][x] = l;
        }
        __syncthreads();
        if (wid == c) {
#pragma unroll
            for (int ks = 0; ks < 8; ++ks)
#pragma unroll
                for (int mi = 0; mi < 2; ++mi) {
                    int m = mi * 16 + (lane & 15);
                    int col = ks * 16 + (lane >> 4) * 8;
                    ldsm4(ah[ks][mi], smem_u32(&stH[m][col]));
                    ldsm4(al[ks][mi], smem_u32(&stL[m][col]));
                }
        }
    }
    __syncthreads();

    unsigned my_gen = 0;
    {
        int i = blockIdx.x * 256 + tid;
        if (i < BB * HH) {
            unsigned short h, l;
            split1(h0[i], h, l);
            g_hhi[0][i] = h;
            g_hlo[0][i] = l;
        }
    }
    ++my_gen;
    grid_barrier(my_gen);

    int kbase = wid * 128;

    for (int t = 0; t < TT; ++t) {
        float xr = 0.f, xz = 0.f, xn = 0.f;
        if (epv) {
            const float* xgp = g_xg + ((size_t)eb * TT + t) * (3 * HH);
            xr = xgp[ej]; xz = xgp[ej + HH]; xn = xgp[ej + 2 * HH];
        }
        {
            const uint4* hi = (const uint4*)&g_hhi[t & 1][0];
            const uint4* lo = (const uint4*)&g_hlo[t & 1][0];
#pragma unroll
            for (int i = 0; i < 4; ++i) {
                int idx = tid + i * 256;
                int b = idx >> 7, k8 = (idx & 127) * 8;
                *(uint4*)&sHh[b][k8] = hi[idx];
                *(uint4*)&sHl[b][k8] = lo[idx];
            }
        }
        __syncthreads();

        float a0[2][4], a1[2][4], a2[2][4];
#pragma unroll
        for (int mi = 0; mi < 2; ++mi)
#pragma unroll
            for (int q = 0; q < 4; ++q) { a0[mi][q] = 0.f; a1[mi][q] = 0.f; a2[mi][q] = 0.f; }

#pragma unroll
        for (int ks = 0; ks < 8; ++ks) {
            int kk = kbase + ks * 16;
            unsigned bh[2], bl[2];
            int r = lane & 15;
            ldsm2(bh, smem_u32(&sHh[r & 7][kk + (r >> 3) * 8]));
            ldsm2(bl, smem_u32(&sHl[r & 7][kk + (r >> 3) * 8]));
#pragma unroll
            for (int mi = 0; mi < 2; ++mi) {
                mma16816(a0[mi], ah[ks][mi], bh);
                mma16816(a1[mi], ah[ks][mi], bl);
                mma16816(a2[mi], al[ks][mi], bh);
            }
        }
        int gr = lane >> 2, gc = (lane & 3) * 2;
#pragma unroll
        for (int mi = 0; mi < 2; ++mi) {
            sRed[wid][mi * 16 + gr][gc]         = a0[mi][0] + a1[mi][0] + a2[mi][0];
            sRed[wid][mi * 16 + gr][gc + 1]     = a0[mi][1] + a1[mi][1] + a2[mi][1];
            sRed[wid][mi * 16 + gr + 8][gc]     = a0[mi][2] + a1[mi][2] + a2[mi][2];
            sRed[wid][mi * 16 + gr + 8][gc + 1] = a0[mi][3] + a1[mi][3] + a2[mi][3];
        }
        __syncthreads();
        {
            int row = tid >> 3, col = tid & 7;
            float s = 0.f;
#pragma unroll
            for (int w = 0; w < 8; ++w) s += sRed[w][row][col];
            sG[row][col] = s;
        }
        __syncthreads();
        if (epv) {
            float sr = sG[eu * 3 + 0][eb];
            float sz = sG[eu * 3 + 1][eb];
            float sn = sG[eu * 3 + 2][eb];
            float r = 1.f / (1.f + __expf(-(xr + sr + br_)));
            float z = 1.f / (1.f + __expf(-(xz + sz + bz_)));
            float n = tanhf(xn + r * (sn + bn_));
            float hnew = (1.f - z) * n + z * hprev;
            hprev = hnew;
            unsigned short hh_, hl_;
            split1(hnew, hh_, hl_);
            g_hhi[(t + 1) & 1][eb * HH + ej] = hh_;
            g_hlo[(t + 1) & 1][eb * HH + ej] = hl_;
            g_emb2[((size_t)(eb * CC + ec) * TT + t) * 8 + ef] = hnew;
            if (t == TT - 1) outHT[eb * HH + ej] = hnew;
        }
        ++my_gen;
        grid_barrier(my_gen);
    }
}

// ---------------- pconvP: P = W @ x + bias (no skip), f32x2 ----------------
__global__ __launch_bounds__(256) void k_pconvP(float* __restrict__ out,
                                                const float* __restrict__ in,
                                                const float* __restrict__ W,
                                                const float* __restrict__ bias,
                                                int TF)
{
    __shared__ __align__(16) float Xs[128][64];
    __shared__ __align__(16) float Ws[16][128];
    int tid = threadIdx.x;
    int tx = tid & 15, ty = tid >> 4;
    int b = blockIdx.y;
    int p0 = blockIdx.x * 64;

#pragma unroll
    for (int i = 0; i < 8; ++i) {
        int e4 = tid + i * 256;
        int ch = e4 >> 4, pq = (e4 & 15) << 2;
        *(float4*)&Xs[ch][pq] = *(const float4*)&in[(size_t)(b * CC + ch) * TF + p0 + pq];
    }
    ull acc2[4][4];
#pragma unroll
    for (int p = 0; p < 4; ++p)
#pragma unroll
        for (int q = 0; q < 4; ++q) acc2[p][q] = 0ull;

    for (int kb = 0; kb < CC; kb += 16) {
#pragma unroll
        for (int i = 0; i < 2; ++i) {
            int e4 = tid * 2 + i;
            int oc = e4 >> 2, k4 = (e4 & 3) << 2;
            float4 v = *(const float4*)&W[oc * CC + kb + k4];
            Ws[k4 + 0][oc] = v.x; Ws[k4 + 1][oc] = v.y;
            Ws[k4 + 2][oc] = v.z; Ws[k4 + 3][oc] = v.w;
        }
        __syncthreads();
#pragma unroll
        for (int kk = 0; kk < 16; ++kk) {
            float4 xv = *(const float4*)&Xs[kb + kk][tx * 4];
            ull dx[4];
            dx[0] = dup2(xv.x); dx[1] = dup2(xv.y);
            dx[2] = dup2(xv.z); dx[3] = dup2(xv.w);
            ull wp[4];
#pragma unroll
            for (int p = 0; p < 4; ++p)
                wp[p] = *(const ull*)&Ws[kk][ty * 8 + 2 * p];
#pragma unroll
            for (int p = 0; p < 4; ++p)
#pragma unroll
                for (int q = 0; q < 4; ++q)
                    acc2[p][q] = ffma2(wp[p], dx[q], acc2[p][q]);
        }
        __syncthreads();
    }
#pragma unroll
    for (int p = 0; p < 4; ++p) {
        int oc0 = ty * 8 + 2 * p, oc1 = oc0 + 1;
        float2 u0 = unpk2(acc2[p][0]), u1 = unpk2(acc2[p][1]);
        float2 u2 = unpk2(acc2[p][2]), u3 = unpk2(acc2[p][3]);
        size_t i0 = (size_t)(b * CC + oc0) * TF + p0 + tx * 4;
        size_t i1 = (size_t)(b * CC + oc1) * TF + p0 + tx * 4;
        float bv0 = bias[oc0], bv1 = bias[oc1];
        float4 o0, o1;
        o0.x = u0.x + bv0; o0.y = u1.x + bv0;
        o0.z = u2.x + bv0; o0.w = u3.x + bv0;
        o1.x = u0.y + bv1; o1.y = u1.y + bv1;
        o1.z = u2.y + bv1; o1.w = u3.y + bv1;
        *(float4*)&out[i0] = o0;
        *(float4*)&out[i1] = o1;
    }
}

// ---------------- weight transpose for convt ----------------
__global__ __launch_bounds__(256) void k_wtT(const float* __restrict__ src,
                                             float* __restrict__ dst)
{
    int i = blockIdx.x * 256 + threadIdx.x;
    if (i < 3 * CC * CC) {
        int oc = i & 127, ic = (i >> 7) & 127, tap = i >> 14;
        dst[i] = src[(oc * CC + ic) * 3 + tap];
    }
}

// ---------------- convt (k=3,s=2) + ReLU, fused skip-add input, f32x2 ---------
__global__ __launch_bounds__(128) void k_convt(float* __restrict__ out,
                                               const float* __restrict__ in,
                                               const float* __restrict__ skip,
                                               const float* __restrict__ wT,
                                               const float* __restrict__ bias,
                                               int Fin, int TF)
{
    __shared__ __align__(16) float Xs[128][36];
    __shared__ __align__(16) float Ws[3][16][128];
    int tid = threadIdx.x;
    int tx = tid & 7, ty = tid >> 3;
    int b = blockIdx.y;
    int p0 = blockIdx.x * 32;

#pragma unroll
    for (int i = 0; i < 8; ++i) {
        int e4 = tid + i * 128;
        int ch = e4 >> 3, pq = (e4 & 7) << 2;
        size_t gi = (size_t)(b * CC + ch) * TF + p0 + pq;
        float4 a = *(const float4*)&in[gi];
        float4 s = *(const float4*)&skip[gi];
        a.x += s.x; a.y += s.y; a.z += s.z; a.w += s.w;
        *(float4*)&Xs[ch][pq] = a;
    }
    int p_ = tx * 4;
    bool sh[4];
#pragma unroll
    for (int jj = 0; jj < 4; ++jj) sh[jj] = (((p_ + jj) & (Fin - 1)) != Fin - 1);

    ull ae2[4][4], ao2[4][4];
#pragma unroll
    for (int p = 0; p < 4; ++p)
#pragma unroll
        for (int q = 0; q < 4; ++q) { ae2[p][q] = 0ull; ao2[p][q] = 0ull; }

    for (int kb = 0; kb < CC; kb += 16) {
        __syncthreads();
#pragma unroll
        for (int i = 0; i < 12; ++i) {
            int idx = tid + i * 128;
            int tap = idx / 512, rem = idx & 511;
            int kkk = rem >> 5, oc4 = (rem & 31) << 2;
            *(float4*)&Ws[tap][kkk][oc4] =
                *(const float4*)&wT[(tap * CC + kb + kkk) * CC + oc4];
        }
        __syncthreads();
#pragma unroll
        for (int kk = 0; kk < 16; ++kk) {
            const float* xrow = &Xs[kb + kk][0];
            float4 xv = *(const float4*)&xrow[p_];
            float xnext = xrow[p_ + 4];
            ull dx[4], dxs[4];
            dx[0] = dup2(xv.x); dx[1] = dup2(xv.y);
            dx[2] = dup2(xv.z); dx[3] = dup2(xv.w);
            dxs[0] = dup2(sh[0] ? xv.y : 0.f);
            dxs[1] = dup2(sh[1] ? xv.z : 0.f);
            dxs[2] = dup2(sh[2] ? xv.w : 0.f);
            dxs[3] = dup2(sh[3] ? xnext : 0.f);
            ull w0p[4], w1p[4], w2p[4];
#pragma unroll
            for (int p = 0; p < 4; ++p) {
                w0p[p] = *(const ull*)&Ws[0][kk][ty * 8 + 2 * p];
                w1p[p] = *(const ull*)&Ws[1][kk][ty * 8 + 2 * p];
                w2p[p] = *(const ull*)&Ws[2][kk][ty * 8 + 2 * p];
            }
#pragma unroll
            for (int p = 0; p < 4; ++p)
#pragma unroll
                for (int q = 0; q < 4; ++q) {
                    ae2[p][q] = ffma2(w1p[p], dx[q], ae2[p][q]);
                    ao2[p][q] = ffma2(w0p[p], dx[q], ao2[p][q]);
                    ao2[p][q] = ffma2(w2p[p], dxs[q], ao2[p][q]);
                }
        }
    }
    int TF2 = TF * 2;
#pragma unroll
    for (int p = 0; p < 4; ++p) {
        int oc0 = ty * 8 + 2 * p, oc1 = oc0 + 1;
        float bv0 = bias[oc0], bv1 = bias[oc1];
#pragma unroll
        for (int q = 0; q < 4; ++q) {
            int pp = p0 + p_ + q;
            float2 e = unpk2(ae2[p][q]);
            float2 o = unpk2(ao2[p][q]);
            float2 r0, r1;
            r0.x = fmaxf(e.x + bv0, 0.f); r0.y = fmaxf(o.x + bv0, 0.f);
            r1.x = fmaxf(e.y + bv1, 0.f); r1.y = fmaxf(o.y + bv1, 0.f);
            *(float2*)&out[(size_t)(b * CC + oc0) * TF2 + 2 * pp] = r0;
            *(float2*)&out[(size_t)(b * CC + oc1) * TF2 + 2 * pp] = r1;
        }
    }
}

// ---------------- final lite: pre = P0 + e1x ; m = sigmoid(conv3(pre)) -------
__global__ __launch_bounds__(256) void k_final_lite(const float* __restrict__ P0,
                                                    const float* __restrict__ w0o,
                                                    const float* __restrict__ b0o,
                                                    float* __restrict__ outm)
{
    __shared__ __align__(16) float pre[128][68];
    __shared__ float wo[128][3];
    const int TF = TT * 64;
    int tid = threadIdx.x;
    int b = blockIdx.y, t = blockIdx.x;
    int p0 = t * 64;

    for (int i = tid; i < 384; i += 256) wo[i / 3][i % 3] = w0o[i];
#pragma unroll
    for (int i = 0; i < 8; ++i) {
        int e4 = tid + i * 256;
        int ch = e4 >> 4, pq = (e4 & 15) << 2;
        size_t gi = (size_t)(b * CC + ch) * TF + p0 + pq;
        float4 a = *(const float4*)&P0[gi];
        float4 s = *(const float4*)&g_e1x[gi];
        a.x += s.x; a.y += s.y; a.z += s.z; a.w += s.w;
        *(float4*)&pre[ch][pq] = a;
    }
    __syncthreads();
    int f = tid >> 2, q = tid & 3;
    float s = 0.f;
#pragma unroll 4
    for (int i = 0; i < 32; ++i) {
        int ch = q * 32 + i;
        float x0 = pre[ch][f];
        float xm = (f > 0) ? pre[ch][f - 1] : 0.f;
        float xp = (f < 63) ? pre[ch][f + 1] : 0.f;
        s = fmaf(wo[ch][0], xm, s);
        s = fmaf(wo[ch][1], x0, s);
        s = fmaf(wo[ch][2], xp, s);
    }
    s += __shfl_down_sync(0xffffffffu, s, 1);
    s += __shfl_down_sync(0xffffffffu, s, 2);
    if (q == 0) outm[((size_t)b * TT + t) * 64 + f] = 1.f / (1.f + __expf(-(s + b0o[0])));
}

// ---------------------------------- launch ----------------------------------
extern "C" void kernel_launch(void* const* d_in, const int* in_sizes, int n_in,
                              void* d_out, int out_size)
{
    const float* emb   = (const float*)d_in[0];
    const float* e3    = (const float*)d_in[1];
    const float* e2    = (const float*)d_in[2];
    const float* e1    = (const float*)d_in[3];
    const float* e0    = (const float*)d_in[4];
    const float* h_erb = (const float*)d_in[5];
    const float* Wih   = (const float*)d_in[6];
    const float* Whh   = (const float*)d_in[7];
    const float* bih   = (const float*)d_in[8];
    const float* bhh   = (const float*)d_in[9];
    const float* w3p   = (const float*)d_in[10];
    const float* b3p   = (const float*)d_in[11];
    const float* w2p   = (const float*)d_in[12];
    const float* b2p   = (const float*)d_in[13];
    const float* w1p   = (const float*)d_in[14];
    const float* b1p   = (const float*)d_in[15];
    const float* w0p   = (const float*)d_in[16];
    const float* b0p   = (const float*)d_in[17];
    const float* wt3   = (const float*)d_in[18];
    const float* bt3   = (const float*)d_in[19];
    const float* wt2   = (const float*)d_in[20];
    const float* bt2   = (const float*)d_in[21];
    const float* wt1   = (const float*)d_in[22];
    const float* bt1   = (const float*)d_in[23];
    const float* w0o   = (const float*)d_in[24];
    const float* b0o   = (const float*)d_in[25];
    float* out = (float*)d_out;

    float* gx3;  cudaGetSymbolAddress((void**)&gx3,  g_x3);
    float* ge3x; cudaGetSymbolAddress((void**)&ge3x, g_e3x);
    float* gx2;  cudaGetSymbolAddress((void**)&gx2,  g_x2);
    float* ge2x; cudaGetSymbolAddress((void**)&ge2x, g_e2x);
    float* gx1;  cudaGetSymbolAddress((void**)&gx1,  g_x1);
    float* ge1x; cudaGetSymbolAddress((void**)&ge1x, g_e1x);
    float* gp0;  cudaGetSymbolAddress((void**)&gp0,  g_p0);
    float* gemb2;cudaGetSymbolAddress((void**)&gemb2,g_emb2);
    float* gw3;  cudaGetSymbolAddress((void**)&gw3,  g_wtT3);
    float* gw2;  cudaGetSymbolAddress((void**)&gw2,  g_wtT2);
    float* gw1;  cudaGetSymbolAddress((void**)&gw1,  g_wtT1);
    void *pAh, *pAl, *pWh, *pWl;
    cudaGetSymbolAddress(&pAh, g_Ah);
    cudaGetSymbolAddress(&pAl, g_Al);
    cudaGetSymbolAddress(&pWh, g_Wh);
    cudaGetSymbolAddress(&pWl, g_Wl);

    cudaFuncSetAttribute(k_gru, cudaFuncAttributeMaxDynamicSharedMemorySize, GRU_SMEM);

    static cudaStream_t s2 = nullptr;
    static cudaEvent_t evF = nullptr, evJ = nullptr;
    if (s2 == nullptr) {
        cudaStreamCreateWithFlags(&s2, cudaStreamNonBlocking);
        cudaEventCreateWithFlags(&evF, cudaEventDisableTiming);
        cudaEventCreateWithFlags(&evJ, cudaEventDisableTiming);
    }

    // side stream: weight transposes + skip-free pconv GEMMs
    cudaEventRecord(evF, 0);
    cudaStreamWaitEvent(s2, evF, 0);
    k_wtT<<<192, 256, 0, s2>>>(wt3, gw3);
    k_wtT<<<192, 256, 0, s2>>>(wt2, gw2);
    k_wtT<<<192, 256, 0, s2>>>(wt1, gw1);
    k_pconvP<<<dim3(64, 8),  256, 0, s2>>>(gx3, e3, w3p, b3p, TT * 8);
    k_pconvP<<<dim3(128, 8), 256, 0, s2>>>(gx2, e2, w2p, b2p, TT * 16);
    k_pconvP<<<dim3(256, 8), 256, 0, s2>>>(gx1, e1, w1p, b1p, TT * 32);
    k_pconvP<<<dim3(512, 8), 256, 0, s2>>>(gp0, e0, w0p, b0p, TT * 64);
    cudaEventRecord(evJ, s2);

    // main stream: GRU pipeline
    k_split<<<4096, 256>>>((const float4*)emb,
                           (ushort4*)pAh, (ushort4*)pAl, 1048576);
    k_split<<<3072, 256>>>((const float4*)Wih,
                           (ushort4*)pWh, (ushort4*)pWl, 786432);
    k_xg_mma<<<dim3(48, 32), 256>>>(bih);
    k_reset<<<19, 256>>>();
    k_gru<<<GBLK, 256, GRU_SMEM>>>(h_erb, Whh, bhh, out + BB * TT * 64);

    // join, then sequential convt chain with fused skip-adds
    cudaStreamWaitEvent(0, evJ, 0);
    k_convt<<<dim3(128, 8), 128>>>(ge3x, gx3, gemb2, gw3, bt3, 8, TT * 8);
    k_convt<<<dim3(256, 8), 128>>>(ge2x, gx2, ge3x, gw2, bt2, 16, TT * 16);
    k_convt<<<dim3(512, 8), 128>>>(ge1x, gx1, ge2x, gw1, bt1, 32, TT * 32);
    k_final_lite<<<dim3(512, 8), 256>>>(gp0, w0o, b0o, out);
}

// round 17
// speedup vs baseline: 1.1438x; 1.1438x over previous
#include <cuda_runtime.h>
#include <cuda_bf16.h>

#define BB 8
#define TT 512
#define CC 128
#define HH 1024
#define GBLK 148
#define GW 7

typedef unsigned long long ull;
typedef unsigned short ushort_t;

// ---------------- f32x2 helpers (decoder kernels) ----------------
__device__ __forceinline__ ull dup2(float x)
{
    ull r;
    asm("mov.b64 %0, {%1, %1};" : "=l"(r) : "f"(x));
    return r;
}
__device__ __forceinline__ ull ffma2(ull a, ull b, ull c)
{
    ull d;
    asm("fma.rn.f32x2 %0, %1, %2, %3;" : "=l"(d) : "l"(a), "l"(b), "l"(c));
    return d;
}
__device__ __forceinline__ float2 unpk2(ull v)
{
    float2 f;
    asm("mov.b64 {%0, %1}, %2;" : "=f"(f.x), "=f"(f.y) : "l"(v));
    return f;
}

// ---------------- static scratch ----------------
__device__ float g_xg[BB * TT * 3 * HH];
__device__ ushort_t g_hhi[2][BB * HH];
__device__ ushort_t g_hlo[2][BB * HH];
__device__ float g_emb2[BB * CC * TT * 8];
__device__ float g_x3[BB * CC * TT * 8];
__device__ float g_e3x[BB * CC * TT * 16];
__device__ float g_x2[BB * CC * TT * 16];
__device__ float g_e2x[BB * CC * TT * 32];
__device__ float g_x1[BB * CC * TT * 32];
__device__ float g_e1x[BB * CC * TT * 64];
__device__ float g_p0[BB * CC * TT * 64];
__device__ float g_wtT3[3 * CC * CC];
__device__ float g_wtT2[3 * CC * CC];
__device__ float g_wtT1[3 * CC * CC];
__device__ unsigned short g_Ah[BB * TT * HH];
__device__ unsigned short g_Al[BB * TT * HH];
__device__ unsigned short g_Wh[3 * HH * HH];
__device__ unsigned short g_Wl[3 * HH * HH];
__device__ unsigned g_bar_count;
__device__ unsigned g_bar_gen;

// ---------------- barrier state reset (per launch) ----------------
__global__ void k_reset()
{
    if (threadIdx.x == 0) { g_bar_count = 0; g_bar_gen = 0; }
}

// ---------------- acquire/release grid barrier (acq_rel arrival) --------------
__device__ __forceinline__ void grid_barrier(unsigned my_gen)
{
    __syncthreads();
    if (threadIdx.x == 0) {
        unsigned arr;
        asm volatile("atom.add.acq_rel.gpu.u32 %0, [%1], 1;"
                     : "=r"(arr) : "l"(&g_bar_count) : "memory");
        if (arr == GBLK - 1) {
            g_bar_count = 0;
            asm volatile("st.release.gpu.u32 [%0], %1;"
                         :: "l"(&g_bar_gen), "r"(my_gen) : "memory");
        } else {
            unsigned cur;
            do {
                asm volatile("ld.acquire.gpu.u32 %0, [%1];"
                             : "=r"(cur) : "l"(&g_bar_gen) : "memory");
            } while ((int)(cur - my_gen) < 0);
        }
    }
    __syncthreads();
}

// ---------------- splitting helper ----------------
__device__ __forceinline__ void split1(float v, unsigned short& h, unsigned short& l)
{
    __nv_bfloat16 bh = __float2bfloat16(v);
    float r = v - __bfloat162float(bh);
    __nv_bfloat16 bl = __float2bfloat16(r);
    h = *(unsigned short*)&bh;
    l = *(unsigned short*)&bl;
}

// ---------------- bf16 hi/lo split: fp32 tensor -> (hi, lo) ----------------
__global__ __launch_bounds__(256) void k_split(const float4* __restrict__ src,
                                               ushort4* __restrict__ hi,
                                               ushort4* __restrict__ lo,
                                               int n4)
{
    int i = blockIdx.x * 256 + threadIdx.x;
    if (i >= n4) return;
    float4 v = src[i];
    float f[4] = { v.x, v.y, v.z, v.w };
    unsigned short h[4], l[4];
#pragma unroll
    for (int q = 0; q < 4; ++q) split1(f[q], h[q], l[q]);
    hi[i] = make_ushort4(h[0], h[1], h[2], h[3]);
    lo[i] = make_ushort4(l[0], l[1], l[2], l[3]);
}

// ---------------- mma helpers (sm_80-baseline PTX) ----------------
__device__ __forceinline__ unsigned smem_u32(const void* p)
{
    unsigned a;
    asm("{ .reg .u64 t; cvta.to.shared.u64 t, %1; cvt.u32.u64 %0, t; }"
        : "=r"(a) : "l"(p));
    return a;
}
__device__ __forceinline__ void ldsm4(unsigned* r, unsigned addr)
{
    asm volatile("ldmatrix.sync.aligned.m8n8.x4.shared.b16 {%0,%1,%2,%3}, [%4];"
        : "=r"(r[0]), "=r"(r[1]), "=r"(r[2]), "=r"(r[3]) : "r"(addr));
}
__device__ __forceinline__ void ldsm2(unsigned* r, unsigned addr)
{
    asm volatile("ldmatrix.sync.aligned.m8n8.x2.shared.b16 {%0,%1}, [%2];"
        : "=r"(r[0]), "=r"(r[1]) : "r"(addr));
}
__device__ __forceinline__ void mma16816(float* d, const unsigned* a, const unsigned* b)
{
    asm volatile("mma.sync.aligned.m16n8k16.row.col.f32.bf16.bf16.f32 "
        "{%0,%1,%2,%3}, {%4,%5,%6,%7}, {%8,%9}, {%0,%1,%2,%3};"
        : "+f"(d[0]), "+f"(d[1]), "+f"(d[2]), "+f"(d[3])
        : "r"(a[0]), "r"(a[1]), "r"(a[2]), "r"(a[3]), "r"(b[0]), "r"(b[1]));
}

// ---------------- xg = emb @ Wih^T + bih : mma.sync split-bf16 ----------------
__global__ __launch_bounds__(256) void k_xg_mma(const float* __restrict__ bias)
{
    __shared__ __align__(16) unsigned short sAh[128][40];
    __shared__ __align__(16) unsigned short sAl[128][40];
    __shared__ __align__(16) unsigned short sWh[64][40];
    __shared__ __align__(16) unsigned short sWl[64][40];
    int tid = threadIdx.x, lane = tid & 31, wid = tid >> 5;
    int wm = wid >> 1, wn = wid & 1;
    int m0 = blockIdx.y * 128, n0 = blockIdx.x * 64;

    float acc[2][4][4];
#pragma unroll
    for (int mi = 0; mi < 2; ++mi)
#pragma unroll
        for (int ni = 0; ni < 4; ++ni)
#pragma unroll
            for (int q = 0; q < 4; ++q) acc[mi][ni][q] = 0.f;

    for (int kc = 0; kc < HH; kc += 32) {
        __syncthreads();
#pragma unroll
        for (int i = 0; i < 6; ++i) {
            int idx = tid + i * 256;
            const uint4* src;
            unsigned short* dst;
            if (idx < 512) {
                int row = idx >> 2, c8 = (idx & 3) * 8;
                src = (const uint4*)&g_Ah[(size_t)(m0 + row) * HH + kc + c8];
                dst = &sAh[row][c8];
            } else if (idx < 1024) {
                int e = idx - 512;
                int row = e >> 2, c8 = (e & 3) * 8;
                src = (const uint4*)&g_Al[(size_t)(m0 + row) * HH + kc + c8];
                dst = &sAl[row][c8];
            } else if (idx < 1280) {
                int e = idx - 1024;
                int row = e >> 2, c8 = (e & 3) * 8;
                src = (const uint4*)&g_Wh[(size_t)(n0 + row) * HH + kc + c8];
                dst = &sWh[row][c8];
            } else {
                int e = idx - 1280;
                int row = e >> 2, c8 = (e & 3) * 8;
                src = (const uint4*)&g_Wl[(size_t)(n0 + row) * HH + kc + c8];
                dst = &sWl[row][c8];
            }
            *(uint4*)dst = *src;
        }
        __syncthreads();

#pragma unroll
        for (int ks = 0; ks < 2; ++ks) {
            int k0 = ks * 16;
            unsigned ah[2][4], al[2][4];
#pragma unroll
            for (int mi = 0; mi < 2; ++mi) {
                int m = wm * 32 + mi * 16 + (lane & 15);
                int kk = k0 + (lane >> 4) * 8;
                ldsm4(ah[mi], smem_u32(&sAh[m][kk]));
                ldsm4(al[mi], smem_u32(&sAl[m][kk]));
            }
            unsigned bh[4][2], bl[4][2];
#pragma unroll
            for (int ni = 0; ni < 4; ++ni) {
                int r = lane & 15;
                int n = wn * 32 + ni * 8 + (r & 7);
                int kk = k0 + (r >> 3) * 8;
                ldsm2(bh[ni], smem_u32(&sWh[n][kk]));
                ldsm2(bl[ni], smem_u32(&sWl[n][kk]));
            }
#pragma unroll
            for (int mi = 0; mi < 2; ++mi)
#pragma unroll
                for (int ni = 0; ni < 4; ++ni) {
                    mma16816(acc[mi][ni], ah[mi], bh[ni]);
                    mma16816(acc[mi][ni], ah[mi], bl[ni]);
                    mma16816(acc[mi][ni], al[mi], bh[ni]);
                }
        }
    }
    int gr = lane >> 2, gc = (lane & 3) * 2;
#pragma unroll
    for (int mi = 0; mi < 2; ++mi)
#pragma unroll
        for (int ni = 0; ni < 4; ++ni) {
            int m = m0 + wm * 32 + mi * 16 + gr;
            int n = n0 + wn * 32 + ni * 8 + gc;
            float b0 = bias[n], b1 = bias[n + 1];
            float2 v0 = { acc[mi][ni][0] + b0, acc[mi][ni][1] + b1 };
            float2 v1 = { acc[mi][ni][2] + b0, acc[mi][ni][3] + b1 };
            *(float2*)&g_xg[(size_t)m * (3 * HH) + n] = v0;
            *(float2*)&g_xg[(size_t)(m + 8) * (3 * HH) + n] = v1;
        }
}

// ---------------- persistent GRU: reg-resident weight fragments ----------------
#define GRU_STRIDE 1032
#define OFF_HH 0
#define OFF_HL 16512
#define OFF_RED 33024
#define GRU_SMEM 41216
#define ST_STRIDE 136

__global__ __launch_bounds__(256) void k_gru(const float* __restrict__ h0,
                                             const float* __restrict__ Whh,
                                             const float* __restrict__ bhh,
                                             float* __restrict__ outHT)
{
    extern __shared__ char gsm[];
    ushort_t (*sHh)[GRU_STRIDE] = (ushort_t(*)[GRU_STRIDE])(gsm + OFF_HH);
    ushort_t (*sHl)[GRU_STRIDE] = (ushort_t(*)[GRU_STRIDE])(gsm + OFF_HL);
    float (*sRed)[32][8] = (float(*)[32][8])(gsm + OFF_RED);
    ushort_t (*stH)[ST_STRIDE] = (ushort_t(*)[ST_STRIDE])(gsm + 0);
    ushort_t (*stL)[ST_STRIDE] = (ushort_t(*)[ST_STRIDE])(gsm + 32 * ST_STRIDE * 2);

    int tid = threadIdx.x, lane = tid & 31, wid = tid >> 5;

    int eu = tid >> 3, eb = tid & 7;
    int ej = blockIdx.x * GW + eu;
    bool epv = (tid < 56) && (ej < HH);
    float br_ = 0.f, bz_ = 0.f, bn_ = 0.f, hprev = 0.f;
    int ec = ej & 127, ef = ej >> 7;
    if (epv) {
        br_ = bhh[ej]; bz_ = bhh[ej + HH]; bn_ = bhh[ej + 2 * HH];
        hprev = h0[eb * HH + ej];
    }

    // prologue: weight fragments -> registers via staged chunks
    unsigned ah[8][2][4], al[8][2][4];
    for (int c = 0; c < 8; ++c) {
        __syncthreads();
        for (int idx = tid; idx < 4096; idx += 256) {
            int row = idx >> 7, x = idx & 127;
            float v = 0.f;
            if (row < 21) {
                int unit = row / 3, gate = row - unit * 3;
                int j = blockIdx.x * GW + unit;
                if (j < HH) v = Whh[(size_t)(j + gate * HH) * HH + c * 128 + x];
            }
            unsigned short h, l;
            split1(v, h, l);
            stH[row][x] = h;
            stL[row][x] = l;
        }
        __syncthreads();
        if (wid == c) {
#pragma unroll
            for (int ks = 0; ks < 8; ++ks)
#pragma unroll
                for (int mi = 0; mi < 2; ++mi) {
                    int m = mi * 16 + (lane & 15);
                    int col = ks * 16 + (lane >> 4) * 8;
                    ldsm4(ah[ks][mi], smem_u32(&stH[m][col]));
                    ldsm4(al[ks][mi], smem_u32(&stL[m][col]));
                }
        }
    }
    __syncthreads();

    unsigned my_gen = 0;
    {
        int i = blockIdx.x * 256 + tid;
        if (i < BB * HH) {
            unsigned short h, l;
            split1(h0[i], h, l);
            g_hhi[0][i] = h;
            g_hlo[0][i] = l;
        }
    }
    ++my_gen;
    grid_barrier(my_gen);

    int kbase = wid * 128;

    for (int t = 0; t < TT; ++t) {
        float xr = 0.f, xz = 0.f, xn = 0.f;
        if (epv) {
            const float* xgp = g_xg + ((size_t)eb * TT + t) * (3 * HH);
            xr = xgp[ej]; xz = xgp[ej + HH]; xn = xgp[ej + 2 * HH];
        }
        {
            const uint4* hi = (const uint4*)&g_hhi[t & 1][0];
            const uint4* lo = (const uint4*)&g_hlo[t & 1][0];
#pragma unroll
            for (int i = 0; i < 4; ++i) {
                int idx = tid + i * 256;
                int b = idx >> 7, k8 = (idx & 127) * 8;
                *(uint4*)&sHh[b][k8] = hi[idx];
                *(uint4*)&sHl[b][k8] = lo[idx];
            }
        }
        __syncthreads();

        float a0[2][4], a1[2][4], a2[2][4];
#pragma unroll
        for (int mi = 0; mi < 2; ++mi)
#pragma unroll
            for (int q = 0; q < 4; ++q) { a0[mi][q] = 0.f; a1[mi][q] = 0.f; a2[mi][q] = 0.f; }

#pragma unroll
        for (int ks = 0; ks < 8; ++ks) {
            int kk = kbase + ks * 16;
            unsigned bh[2], bl[2];
            int r = lane & 15;
            ldsm2(bh, smem_u32(&sHh[r & 7][kk + (r >> 3) * 8]));
            ldsm2(bl, smem_u32(&sHl[r & 7][kk + (r >> 3) * 8]));
#pragma unroll
            for (int mi = 0; mi < 2; ++mi) {
                mma16816(a0[mi], ah[ks][mi], bh);
                mma16816(a1[mi], ah[ks][mi], bl);
                mma16816(a2[mi], al[ks][mi], bh);
            }
        }
        int gr = lane >> 2, gc = (lane & 3) * 2;
#pragma unroll
        for (int mi = 0; mi < 2; ++mi) {
            sRed[wid][mi * 16 + gr][gc]         = a0[mi][0] + a1[mi][0] + a2[mi][0];
            sRed[wid][mi * 16 + gr][gc + 1]     = a0[mi][1] + a1[mi][1] + a2[mi][1];
            sRed[wid][mi * 16 + gr + 8][gc]     = a0[mi][2] + a1[mi][2] + a2[mi][2];
            sRed[wid][mi * 16 + gr + 8][gc + 1] = a0[mi][3] + a1[mi][3] + a2[mi][3];
        }
        __syncthreads();
        if (epv) {
            float sr = 0.f, sz = 0.f, sn = 0.f;
#pragma unroll
            for (int w = 0; w < 8; ++w) {
                sr += sRed[w][eu * 3 + 0][eb];
                sz += sRed[w][eu * 3 + 1][eb];
                sn += sRed[w][eu * 3 + 2][eb];
            }
            float r = 1.f / (1.f + __expf(-(xr + sr + br_)));
            float z = 1.f / (1.f + __expf(-(xz + sz + bz_)));
            float n = tanhf(xn + r * (sn + bn_));
            float hnew = (1.f - z) * n + z * hprev;
            hprev = hnew;
            unsigned short hh_, hl_;
            split1(hnew, hh_, hl_);
            g_hhi[(t + 1) & 1][eb * HH + ej] = hh_;
            g_hlo[(t + 1) & 1][eb * HH + ej] = hl_;
            g_emb2[((size_t)(eb * CC + ec) * TT + t) * 8 + ef] = hnew;
            if (t == TT - 1) outHT[eb * HH + ej] = hnew;
        }
        if (t != TT - 1) {
            ++my_gen;
            grid_barrier(my_gen);
        }
    }
}

// ---------------- pconvP: P = W @ x + bias (no skip), f32x2 ----------------
__global__ __launch_bounds__(256) void k_pconvP(float* __restrict__ out,
                                                const float* __restrict__ in,
                                                const float* __restrict__ W,
                                                const float* __restrict__ bias,
                                                int TF)
{
    __shared__ __align__(16) float Xs[128][64];
    __shared__ __align__(16) float Ws[16][128];
    int tid = threadIdx.x;
    int tx = tid & 15, ty = tid >> 4;
    int b = blockIdx.y;
    int p0 = blockIdx.x * 64;

#pragma unroll
    for (int i = 0; i < 8; ++i) {
        int e4 = tid + i * 256;
        int ch = e4 >> 4, pq = (e4 & 15) << 2;
        *(float4*)&Xs[ch][pq] = *(const float4*)&in[(size_t)(b * CC + ch) * TF + p0 + pq];
    }
    ull acc2[4][4];
#pragma unroll
    for (int p = 0; p < 4; ++p)
#pragma unroll
        for (int q = 0; q < 4; ++q) acc2[p][q] = 0ull;

    for (int kb = 0; kb < CC; kb += 16) {
#pragma unroll
        for (int i = 0; i < 2; ++i) {
            int e4 = tid * 2 + i;
            int oc = e4 >> 2, k4 = (e4 & 3) << 2;
            float4 v = *(const float4*)&W[oc * CC + kb + k4];
            Ws[k4 + 0][oc] = v.x; Ws[k4 + 1][oc] = v.y;
            Ws[k4 + 2][oc] = v.z; Ws[k4 + 3][oc] = v.w;
        }
        __syncthreads();
#pragma unroll
        for (int kk = 0; kk < 16; ++kk) {
            float4 xv = *(const float4*)&Xs[kb + kk][tx * 4];
            ull dx[4];
            dx[0] = dup2(xv.x); dx[1] = dup2(xv.y);
            dx[2] = dup2(xv.z); dx[3] = dup2(xv.w);
            ull wp[4];
#pragma unroll
            for (int p = 0; p < 4; ++p)
                wp[p] = *(const ull*)&Ws[kk][ty * 8 + 2 * p];
#pragma unroll
            for (int p = 0; p < 4; ++p)
#pragma unroll
                for (int q = 0; q < 4; ++q)
                    acc2[p][q] = ffma2(wp[p], dx[q], acc2[p][q]);
        }
        __syncthreads();
    }
#pragma unroll
    for (int p = 0; p < 4; ++p) {
        int oc0 = ty * 8 + 2 * p, oc1 = oc0 + 1;
        float2 u0 = unpk2(acc2[p][0]), u1 = unpk2(acc2[p][1]);
        float2 u2 = unpk2(acc2[p][2]), u3 = unpk2(acc2[p][3]);
        size_t i0 = (size_t)(b * CC + oc0) * TF + p0 + tx * 4;
        size_t i1 = (size_t)(b * CC + oc1) * TF + p0 + tx * 4;
        float bv0 = bias[oc0], bv1 = bias[oc1];
        float4 o0, o1;
        o0.x = u0.x + bv0; o0.y = u1.x + bv0;
        o0.z = u2.x + bv0; o0.w = u3.x + bv0;
        o1.x = u0.y + bv1; o1.y = u1.y + bv1;
        o1.z = u2.y + bv1; o1.w = u3.y + bv1;
        *(float4*)&out[i0] = o0;
        *(float4*)&out[i1] = o1;
    }
}

// ---------------- weight transpose for convt ----------------
__global__ __launch_bounds__(256) void k_wtT(const float* __restrict__ src,
                                             float* __restrict__ dst)
{
    int i = blockIdx.x * 256 + threadIdx.x;
    if (i < 3 * CC * CC) {
        int oc = i & 127, ic = (i >> 7) & 127, tap = i >> 14;
        dst[i] = src[(oc * CC + ic) * 3 + tap];
    }
}

// ---------------- convt (k=3,s=2) + ReLU, fused skip-add input, f32x2 ---------
__global__ __launch_bounds__(128) void k_convt(float* __restrict__ out,
                                               const float* __restrict__ in,
                                               const float* __restrict__ skip,
                                               const float* __restrict__ wT,
                                               const float* __restrict__ bias,
                                               int Fin, int TF)
{
    __shared__ __align__(16) float Xs[128][36];
    __shared__ __align__(16) float Ws[3][16][128];
    int tid = threadIdx.x;
    int tx = tid & 7, ty = tid >> 3;
    int b = blockIdx.y;
    int p0 = blockIdx.x * 32;

#pragma unroll
    for (int i = 0; i < 8; ++i) {
        int e4 = tid + i * 128;
        int ch = e4 >> 3, pq = (e4 & 7) << 2;
        size_t gi = (size_t)(b * CC + ch) * TF + p0 + pq;
        float4 a = *(const float4*)&in[gi];
        float4 s = *(const float4*)&skip[gi];
        a.x += s.x; a.y += s.y; a.z += s.z; a.w += s.w;
        *(float4*)&Xs[ch][pq] = a;
    }
    int p_ = tx * 4;
    bool sh[4];
#pragma unroll
    for (int jj = 0; jj < 4; ++jj) sh[jj] = (((p_ + jj) & (Fin - 1)) != Fin - 1);

    ull ae2[4][4], ao2[4][4];
#pragma unroll
    for (int p = 0; p < 4; ++p)
#pragma unroll
        for (int q = 0; q < 4; ++q) { ae2[p][q] = 0ull; ao2[p][q] = 0ull; }

    for (int kb = 0; kb < CC; kb += 16) {
        __syncthreads();
#pragma unroll
        for (int i = 0; i < 12; ++i) {
            int idx = tid + i * 128;
            int tap = idx / 512, rem = idx & 511;
            int kkk = rem >> 5, oc4 = (rem & 31) << 2;
            *(float4*)&Ws[tap][kkk][oc4] =
                *(const float4*)&wT[(tap * CC + kb + kkk) * CC + oc4];
        }
        __syncthreads();
#pragma unroll
        for (int kk = 0; kk < 16; ++kk) {
            const float* xrow = &Xs[kb + kk][0];
            float4 xv = *(const float4*)&xrow[p_];
            float xnext = xrow[p_ + 4];
            ull dx[4], dxs[4];
            dx[0] = dup2(xv.x); dx[1] = dup2(xv.y);
            dx[2] = dup2(xv.z); dx[3] = dup2(xv.w);
            dxs[0] = dup2(sh[0] ? xv.y : 0.f);
            dxs[1] = dup2(sh[1] ? xv.z : 0.f);
            dxs[2] = dup2(sh[2] ? xv.w : 0.f);
            dxs[3] = dup2(sh[3] ? xnext : 0.f);
            ull w0p[4], w1p[4], w2p[4];
#pragma unroll
            for (int p = 0; p < 4; ++p) {
                w0p[p] = *(const ull*)&Ws[0][kk][ty * 8 + 2 * p];
                w1p[p] = *(const ull*)&Ws[1][kk][ty * 8 + 2 * p];
                w2p[p] = *(const ull*)&Ws[2][kk][ty * 8 + 2 * p];
            }
#pragma unroll
            for (int p = 0; p < 4; ++p)
#pragma unroll
                for (int q = 0; q < 4; ++q) {
                    ae2[p][q] = ffma2(w1p[p], dx[q], ae2[p][q]);
                    ao2[p][q] = ffma2(w0p[p], dx[q], ao2[p][q]);
                    ao2[p][q] = ffma2(w2p[p], dxs[q], ao2[p][q]);
                }
        }
    }
    int TF2 = TF * 2;
#pragma unroll
    for (int p = 0; p < 4; ++p) {
        int oc0 = ty * 8 + 2 * p, oc1 = oc0 + 1;
        float bv0 = bias[oc0], bv1 = bias[oc1];
#pragma unroll
        for (int q = 0; q < 4; ++q) {
            int pp = p0 + p_ + q;
            float2 e = unpk2(ae2[p][q]);
            float2 o = unpk2(ao2[p][q]);
            float2 r0, r1;
            r0.x = fmaxf(e.x + bv0, 0.f); r0.y = fmaxf(o.x + bv0, 0.f);
            r1.x = fmaxf(e.y + bv1, 0.f); r1.y = fmaxf(o.y + bv1, 0.f);
            *(float2*)&out[(size_t)(b * CC + oc0) * TF2 + 2 * pp] = r0;
            *(float2*)&out[(size_t)(b * CC + oc1) * TF2 + 2 * pp] = r1;
        }
    }
}

// ---------------- final lite: pre = P0 + e1x ; m = sigmoid(conv3(pre)) -------
__global__ __launch_bounds__(256) void k_final_lite(const float* __restrict__ P0,
                                                    const float* __restrict__ w0o,
                                                    const float* __restrict__ b0o,
                                                    float* __restrict__ outm)
{
    __shared__ __align__(16) float pre[128][68];
    __shared__ float wo[128][3];
    const int TF = TT * 64;
    int tid = threadIdx.x;
    int b = blockIdx.y, t = blockIdx.x;
    int p0 = t * 64;

    for (int i = tid; i < 384; i += 256) wo[i / 3][i % 3] = w0o[i];
#pragma unroll
    for (int i = 0; i < 8; ++i) {
        int e4 = tid + i * 256;
        int ch = e4 >> 4, pq = (e4 & 15) << 2;
        size_t gi = (size_t)(b * CC + ch) * TF + p0 + pq;
        float4 a = *(const float4*)&P0[gi];
        float4 s = *(const float4*)&g_e1x[gi];
        a.x += s.x; a.y += s.y; a.z += s.z; a.w += s.w;
        *(float4*)&pre[ch][pq] = a;
    }
    __syncthreads();
    int f = tid >> 2, q = tid & 3;
    float s = 0.f;
#pragma unroll 4
    for (int i = 0; i < 32; ++i) {
        int ch = q * 32 + i;
        float x0 = pre[ch][f];
        float xm = (f > 0) ? pre[ch][f - 1] : 0.f;
        float xp = (f < 63) ? pre[ch][f + 1] : 0.f;
        s = fmaf(wo[ch][0], xm, s);
        s = fmaf(wo[ch][1], x0, s);
        s = fmaf(wo[ch][2], xp, s);
    }
    s += __shfl_down_sync(0xffffffffu, s, 1);
    s += __shfl_down_sync(0xffffffffu, s, 2);
    if (q == 0) outm[((size_t)b * TT + t) * 64 + f] = 1.f / (1.f + __expf(-(s + b0o[0])));
}

// ---------------------------------- launch ----------------------------------
extern "C" void kernel_launch(void* const* d_in, const int* in_sizes, int n_in,
                              void* d_out, int out_size)
{
    const float* emb   = (const float*)d_in[0];
    const float* e3    = (const float*)d_in[1];
    const float* e2    = (const float*)d_in[2];
    const float* e1    = (const float*)d_in[3];
    const float* e0    = (const float*)d_in[4];
    const float* h_erb = (const float*)d_in[5];
    const float* Wih   = (const float*)d_in[6];
    const float* Whh   = (const float*)d_in[7];
    const float* bih   = (const float*)d_in[8];
    const float* bhh   = (const float*)d_in[9];
    const float* w3p   = (const float*)d_in[10];
    const float* b3p   = (const float*)d_in[11];
    const float* w2p   = (const float*)d_in[12];
    const float* b2p   = (const float*)d_in[13];
    const float* w1p   = (const float*)d_in[14];
    const float* b1p   = (const float*)d_in[15];
    const float* w0p   = (const float*)d_in[16];
    const float* b0p   = (const float*)d_in[17];
    const float* wt3   = (const float*)d_in[18];
    const float* bt3   = (const float*)d_in[19];
    const float* wt2   = (const float*)d_in[20];
    const float* bt2   = (const float*)d_in[21];
    const float* wt1   = (const float*)d_in[22];
    const float* bt1   = (const float*)d_in[23];
    const float* w0o   = (const float*)d_in[24];
    const float* b0o   = (const float*)d_in[25];
    float* out = (float*)d_out;

    float* gx3;  cudaGetSymbolAddress((void**)&gx3,  g_x3);
    float* ge3x; cudaGetSymbolAddress((void**)&ge3x, g_e3x);
    float* gx2;  cudaGetSymbolAddress((void**)&gx2,  g_x2);
    float* ge2x; cudaGetSymbolAddress((void**)&ge2x, g_e2x);
    float* gx1;  cudaGetSymbolAddress((void**)&gx1,  g_x1);
    float* ge1x; cudaGetSymbolAddress((void**)&ge1x, g_e1x);
    float* gp0;  cudaGetSymbolAddress((void**)&gp0,  g_p0);
    float* gemb2;cudaGetSymbolAddress((void**)&gemb2,g_emb2);
    float* gw3;  cudaGetSymbolAddress((void**)&gw3,  g_wtT3);
    float* gw2;  cudaGetSymbolAddress((void**)&gw2,  g_wtT2);
    float* gw1;  cudaGetSymbolAddress((void**)&gw1,  g_wtT1);
    void *pAh, *pAl, *pWh, *pWl;
    cudaGetSymbolAddress(&pAh, g_Ah);
    cudaGetSymbolAddress(&pAl, g_Al);
    cudaGetSymbolAddress(&pWh, g_Wh);
    cudaGetSymbolAddress(&pWl, g_Wl);

    cudaFuncSetAttribute(k_gru, cudaFuncAttributeMaxDynamicSharedMemorySize, GRU_SMEM);

    static cudaStream_t s2 = nullptr;
    static cudaEvent_t evF = nullptr, evJ = nullptr;
    if (s2 == nullptr) {
        cudaStreamCreateWithFlags(&s2, cudaStreamNonBlocking);
        cudaEventCreateWithFlags(&evF, cudaEventDisableTiming);
        cudaEventCreateWithFlags(&evJ, cudaEventDisableTiming);
    }

    // side stream: weight transposes + skip-free pconv GEMMs
    cudaEventRecord(evF, 0);
    cudaStreamWaitEvent(s2, evF, 0);
    k_wtT<<<192, 256, 0, s2>>>(wt3, gw3);
    k_wtT<<<192, 256, 0, s2>>>(wt2, gw2);
    k_wtT<<<192, 256, 0, s2>>>(wt1, gw1);
    k_pconvP<<<dim3(64, 8),  256, 0, s2>>>(gx3, e3, w3p, b3p, TT * 8);
    k_pconvP<<<dim3(128, 8), 256, 0, s2>>>(gx2, e2, w2p, b2p, TT * 16);
    k_pconvP<<<dim3(256, 8), 256, 0, s2>>>(gx1, e1, w1p, b1p, TT * 32);
    k_pconvP<<<dim3(512, 8), 256, 0, s2>>>(gp0, e0, w0p, b0p, TT * 64);
    cudaEventRecord(evJ, s2);

    // main stream: GRU pipeline
    k_split<<<4096, 256>>>((const float4*)emb,
                           (ushort4*)pAh, (ushort4*)pAl, 1048576);
    k_split<<<3072, 256>>>((const float4*)Wih,
                           (ushort4*)pWh, (ushort4*)pWl, 786432);
    k_xg_mma<<<dim3(48, 32), 256>>>(bih);
    k_reset<<<1, 32>>>();
    k_gru<<<GBLK, 256, GRU_SMEM>>>(h_erb, Whh, bhh, out + BB * TT * 64);

    // join, then sequential convt chain with fused skip-adds
    cudaStreamWaitEvent(0, evJ, 0);
    k_convt<<<dim3(128, 8), 128>>>(ge3x, gx3, gemb2, gw3, bt3, 8, TT * 8);
    k_convt<<<dim3(256, 8), 128>>>(ge2x, gx2, ge3x, gw2, bt2, 16, TT * 16);
    k_convt<<<dim3(512, 8), 128>>>(ge1x, gx1, ge2x, gw1, bt1, 32, TT * 32);
    k_final_lite<<<dim3(512, 8), 256>>>(gp0, w0o, b0o, out);
}